// round 14
// baseline (speedup 1.0000x reference)
#include <cuda_runtime.h>
#include <cstdint>

#define MM 2
#define LL 6
#define NN 512
#define HH 64
#define VK 1.0f
#define SIG2 0.01
#define DDIM 2.0
#define NT 2048
#define RMAX 16.0f
#define HSTEP (RMAX / (float)NT)
#define BNODES 64
#define BSTRIDE 63
#define BGRID ((NT + BSTRIDE - 1) / BSTRIDE)   // 33

typedef unsigned long long u64;

__device__ float4 g_tab[NT];        // (phi+b3, dphi, d2, d2-slope) Taylor entries
__device__ float  g_vec[12 * NN * 2];  // per-snapshot gradient accumulators
__device__ double g_slots[64];

__device__ __forceinline__ float tanh_fast(float x) {
    float y; asm("tanh.approx.f32 %0, %1;" : "=f"(y) : "f"(x)); return y;
}
__device__ __forceinline__ u64 pack2(float x) {
    u64 r; asm("mov.b64 %0, {%1,%1};" : "=l"(r) : "f"(x)); return r;
}
__device__ __forceinline__ u64 pack2f(float lo, float hi) {
    u64 r; asm("mov.b64 %0, {%1,%2};" : "=l"(r) : "f"(lo), "f"(hi)); return r;
}
__device__ __forceinline__ void unpack2(u64 v, float& lo, float& hi) {
    asm("mov.b64 {%0,%1}, %2;" : "=f"(lo), "=f"(hi) : "l"(v));
}
__device__ __forceinline__ u64 fma2(u64 a, u64 b, u64 c) {
    u64 d; asm("fma.rn.f32x2 %0, %1, %2, %3;" : "=l"(d) : "l"(a), "l"(b), "l"(c)); return d;
}

// ------- builder (R13) + zero gv/slots -------
__global__ void __launch_bounds__(128)
build_table(const float* __restrict__ w1, const float* __restrict__ b1,
            const float* __restrict__ W2, const float* __restrict__ b2,
            const float* __restrict__ w3, const float* __restrict__ b3p)
{
    __shared__ float sW2[HH * HH];
    __shared__ float sw1[HH], sb1[HH], sb2[HH], sw3[HH];
    __shared__ float sphi[BNODES], sdphi[BNODES], sd2[BNODES];

    int tid = threadIdx.x;
    #pragma unroll
    for (int s = 0; s < HH * HH; s += 128) sW2[s + tid] = W2[s + tid];
    if (tid < HH) { sw1[tid] = w1[tid]; sb1[tid] = b1[tid]; sb2[tid] = b2[tid]; sw3[tid] = w3[tid]; }

    // zero accumulators (grid-stride; kernel boundary orders vs pair kernel)
    for (int idx = blockIdx.x * 128 + tid; idx < 12 * NN * 2; idx += BGRID * 128)
        g_vec[idx] = 0.f;
    if (blockIdx.x == 0 && tid < 64) g_slots[tid] = 0.0;
    __syncthreads();

    int half = tid & 1;
    int pair = tid >> 1;
    int ridx = blockIdx.x * BSTRIDE + pair;
    float r = (float)ridx * HSTEP;

    float h1[HH];
    #pragma unroll
    for (int k = 0; k < HH; k++)
        h1[k] = tanh_fast(fmaf(r, sw1[k], sb1[k]));

    float phi = 0.f, dphi = 0.f, d2phi = 0.f;

    #pragma unroll
    for (int cc = 0; cc < 2; cc++) {
        int c = half * 32 + cc * 16;
        u64 z2[8], zp[8], zpp[8];
        #pragma unroll
        for (int p = 0; p < 8; p++) {
            z2[p]  = pack2f(sb2[c + 2 * p], sb2[c + 2 * p + 1]);
            zp[p]  = 0ull;
            zpp[p] = 0ull;
        }
        #pragma unroll 8
        for (int k = 0; k < HH; k++) {
            float h   = h1[k];
            float w1k = sw1[k];
            float s   = fmaf(-h, h, 1.f);
            float hp  = s * w1k;
            float hpp = -2.f * h * hp * w1k;
            u64 hh   = pack2(h);
            u64 hpx  = pack2(hp);
            u64 hppx = pack2(hpp);
            const ulonglong2* wr = (const ulonglong2*)(sW2 + k * HH + c);
            #pragma unroll
            for (int q = 0; q < 4; q++) {
                ulonglong2 w = wr[q];
                z2[2 * q]      = fma2(w.x, hh,   z2[2 * q]);
                z2[2 * q + 1]  = fma2(w.y, hh,   z2[2 * q + 1]);
                zp[2 * q]      = fma2(w.x, hpx,  zp[2 * q]);
                zp[2 * q + 1]  = fma2(w.y, hpx,  zp[2 * q + 1]);
                zpp[2 * q]     = fma2(w.x, hppx, zpp[2 * q]);
                zpp[2 * q + 1] = fma2(w.y, hppx, zpp[2 * q + 1]);
            }
        }
        #pragma unroll
        for (int p = 0; p < 8; p++) {
            float a0, a1, p0, p1, q0, q1;
            unpack2(z2[p], a0, a1);
            unpack2(zp[p], p0, p1);
            unpack2(zpp[p], q0, q1);
            float w30 = sw3[c + 2 * p], w31 = sw3[c + 2 * p + 1];

            float h2 = tanh_fast(a0);
            phi = fmaf(w30, h2, phi);
            float e   = fmaf(-h2, h2, 1.f);
            float hp2 = e * p0;
            float hq2 = fmaf(e, q0, -2.f * h2 * hp2 * p0);
            dphi  = fmaf(w30, hp2, dphi);
            d2phi = fmaf(w30, hq2, d2phi);

            h2 = tanh_fast(a1);
            phi = fmaf(w31, h2, phi);
            e   = fmaf(-h2, h2, 1.f);
            hp2 = e * p1;
            hq2 = fmaf(e, q1, -2.f * h2 * hp2 * p1);
            dphi  = fmaf(w31, hp2, dphi);
            d2phi = fmaf(w31, hq2, d2phi);
        }
    }

    phi   += __shfl_xor_sync(0xffffffffu, phi,   1);
    dphi  += __shfl_xor_sync(0xffffffffu, dphi,  1);
    d2phi += __shfl_xor_sync(0xffffffffu, d2phi, 1);

    if (half == 0) {
        sphi[pair]  = phi + b3p[0];
        sdphi[pair] = dphi;
        sd2[pair]   = d2phi;
    }
    __syncthreads();

    if (half == 0 && pair < BSTRIDE) {
        int e = blockIdx.x * BSTRIDE + pair;
        if (e < NT)
            g_tab[e] = make_float4(sphi[pair], sdphi[pair], sd2[pair],
                                   sd2[pair + 1] - sd2[pair]);
    }
}

// ------- triangle pair pass: round-robin schedule, each unordered pair once -------
// round t in [0,511): s=0 -> pair (511, t); s in [1,256): i=(t+s)%511, j=(t-s)%511
__global__ void __launch_bounds__(256)
pair_tri(const float* __restrict__ data, const float* __restrict__ t_)
{
    int tid  = threadIdx.x;
    int w    = tid >> 5;
    int lane = tid & 31;
    int bx   = blockIdx.x;           // 0..383
    int sl   = bx >> 5;              // snapshot 0..11
    int rb   = bx & 31;              // round block: rounds rb*16 .. rb*16+15
    int l    = sl % LL;
    bool deriv   = (l < LL - 1);
    bool needphi = (l == 0 || l == LL - 1);

    const float2* snap = (const float2*)(data + (size_t)sl * NN * 2);
    float* gv = g_vec + sl * NN * 2;
    int s = (w << 5) | lane;         // 0..255

    float lap = 0.f, phis = 0.f;
    const float scale = (float)NT / RMAX;

    #pragma unroll 4
    for (int tt = 0; tt < 16; tt++) {
        int t = rb * 16 + tt;
        bool act = (t < 511);
        int i, j;
        if (s == 0) { i = NN - 1; j = t < 511 ? t : 0; }
        else {
            i = t + s;  if (i >= 511) i -= 511;
            j = t - s;  if (j < 0)    j += 511;
        }
        float2 xi = snap[i];
        float2 xj = snap[j];
        float dx = xi.x - xj.x, dy = xi.y - xj.y;
        float ssq = dx * dx + dy * dy;
        float inv = rsqrtf(fmaxf(ssq, 1e-20f));
        float r = ssq * inv;
        float u = r * scale;
        int i0 = (int)u;
        i0 = (i0 > NT - 2) ? (NT - 2) : i0;
        float f = u - (float)i0;
        float4 e = __ldg(&g_tab[i0]);
        float x  = f * HSTEP;
        float d2 = fmaf(f, e.w, e.z);
        float dp = fmaf(x, fmaf(0.5f * f, e.w, e.z), e.y);
        float ph = fmaf(x, fmaf(0.5f * x, fmaf(0.33333333f * f, e.w, e.z), e.y), e.x);

        if (act) {
            if (needphi) phis += ph;
            if (deriv) {
                lap += d2;
                float c  = dp * inv;
                float cx = c * dx, cy = c * dy;
                atomicAdd(&gv[i * 2 + 0],  cx);
                atomicAdd(&gv[i * 2 + 1],  cy);
                atomicAdd(&gv[j * 2 + 0], -cx);
                atomicAdd(&gv[j * 2 + 1], -cy);
            }
        }
    }

    #pragma unroll
    for (int k = 16; k > 0; k >>= 1) {
        lap  += __shfl_xor_sync(0xffffffffu, lap,  k);
        phis += __shfl_xor_sync(0xffffffffu, phis, k);
    }

    if (lane == 0 && (deriv || needphi)) {
        const double invN2 = 1.0 / ((double)NN * NN);
        double contrib = 0.0;
        if (deriv) {
            double dtl = (double)(t_[l + 1] - t_[l]);
            contrib += SIG2 * dtl * 2.0 * (double)lap * invN2;   // lap doubled (symmetric)
        }
        if (needphi) {
            double sign = (l == 0) ? 2.0 : -2.0;
            contrib += sign * 2.0 * (double)phis * invN2;        // phi doubled
        }
        asm volatile("red.release.gpu.global.add.f64 [%0], %1;"
                     :: "l"(&g_slots[(bx * 8 + w) & 63]), "d"(contrib) : "memory");
    }
}

// ------- finalize: drift^2 from gv, V terms, slots, output -------
__global__ void __launch_bounds__(256)
finalize(const float* __restrict__ data, const float* __restrict__ t_,
         float* __restrict__ out)
{
    __shared__ double red[256];
    int tid = threadIdx.x;
    double ssum = 0.0;
    const double invN = 1.0 / (double)NN;

    if (tid < 64) ssum += g_slots[tid];

    // dissipation: m in [0,2), l in [0,5), i in [0,512)
    for (int idx = tid; idx < MM * (LL - 1) * NN; idx += 256) {
        int i   = idx & (NN - 1);
        int dsl = idx >> 9;            // 0..9
        int l   = dsl % (LL - 1);
        int m   = dsl / (LL - 1);
        int sl  = m * LL + l;
        const float* snap = data + (size_t)sl * NN * 2;
        const float* gvp  = g_vec + sl * NN * 2 + i * 2;
        double dtl = (double)(t_[l + 1] - t_[l]);
        double drx = -(double)VK * (double)snap[i * 2 + 0] - (double)gvp[0] * invN;
        double dry = -(double)VK * (double)snap[i * 2 + 1] - (double)gvp[1] * invN;
        ssum += dtl * (drx * drx + dry * dry) * invN;
    }

    // energy V terms at l=0 (+2) and l=5 (-2)
    for (int idx = tid; idx < MM * 2 * NN; idx += 256) {
        int i  = idx & (NN - 1);
        int le = (idx >> 9) & 1;
        int m  = idx >> 10;
        int l  = le ? (LL - 1) : 0;
        double sign = le ? -2.0 : 2.0;
        const float* snap = data + (size_t)(m * LL + l) * NN * 2;
        double x = snap[i * 2 + 0], y = snap[i * 2 + 1];
        ssum += sign * 0.5 * (double)VK * (x * x + y * y) * invN;
    }

    red[tid] = ssum;
    __syncthreads();
    for (int k = 128; k > 0; k >>= 1) {
        if (tid < k) red[tid] += red[tid + k];
        __syncthreads();
    }
    if (tid == 0) {
        double S = red[0];
        S += (double)MM * SIG2 * (double)VK * DDIM * (double)(t_[LL - 1] - t_[0]);
        double res = S / (double)(MM * (LL - 1));
        out[0] = (float)(res * res);
    }
}

extern "C" void kernel_launch(void* const* d_in, const int* in_sizes, int n_in,
                              void* d_out, int out_size)
{
    const float* data = (const float*)d_in[0];
    const float* t    = (const float*)d_in[1];
    const float* w1   = (const float*)d_in[2];
    const float* b1   = (const float*)d_in[3];
    const float* W2   = (const float*)d_in[4];
    const float* b2   = (const float*)d_in[5];
    const float* w3   = (const float*)d_in[6];
    const float* b3   = (const float*)d_in[7];

    build_table<<<BGRID, 128>>>(w1, b1, W2, b2, w3, b3);
    pair_tri<<<12 * 32, 256>>>(data, t);
    finalize<<<1, 256>>>(data, t, (float*)d_out);
}

// round 15
// speedup vs baseline: 1.2803x; 1.2803x over previous
#include <cuda_runtime.h>
#include <cstdint>

#define MM 2
#define LL 6
#define NN 512
#define HH 64
#define VK 1.0f
#define SIG2 0.01
#define DDIM 2.0
#define NT 2048
#define RMAX 16.0f
#define HSTEP (RMAX / (float)NT)
#define BNODES 64
#define BSTRIDE 63
#define BGRID ((NT + BSTRIDE - 1) / BSTRIDE)   // 33
#define JOBS 136                                // 16 tiles -> 136 (a<=b) tile pairs
#define NWJOB (12 * JOBS)                       // 1632 warp jobs

typedef unsigned long long u64;

__device__ float4 g_tab[NT];           // (phi+b3, dphi, d2, d2-slope)
__device__ float  g_vec[12 * NN * 2];  // per-snapshot gradient rows
__device__ double g_slots[64];

__device__ __forceinline__ float tanh_fast(float x) {
    float y; asm("tanh.approx.f32 %0, %1;" : "=f"(y) : "f"(x)); return y;
}
__device__ __forceinline__ u64 pack2(float x) {
    u64 r; asm("mov.b64 %0, {%1,%1};" : "=l"(r) : "f"(x)); return r;
}
__device__ __forceinline__ u64 pack2f(float lo, float hi) {
    u64 r; asm("mov.b64 %0, {%1,%2};" : "=l"(r) : "f"(lo), "f"(hi)); return r;
}
__device__ __forceinline__ void unpack2(u64 v, float& lo, float& hi) {
    asm("mov.b64 {%0,%1}, %2;" : "=f"(lo), "=f"(hi) : "l"(v));
}
__device__ __forceinline__ u64 fma2(u64 a, u64 b, u64 c) {
    u64 d; asm("fma.rn.f32x2 %0, %1, %2, %3;" : "=l"(d) : "l"(a), "l"(b), "l"(c)); return d;
}

// ------- builder: 4-way channel split, h1 in registers -------
__global__ void __launch_bounds__(256)
build_table(const float* __restrict__ w1, const float* __restrict__ b1,
            const float* __restrict__ W2, const float* __restrict__ b2,
            const float* __restrict__ w3, const float* __restrict__ b3p)
{
    __shared__ float sW2[HH * HH];
    __shared__ float sw1[HH], sb1[HH], sb2[HH], sw3[HH];
    __shared__ float sphi[BNODES], sdphi[BNODES], sd2[BNODES];

    int tid = threadIdx.x;
    #pragma unroll
    for (int s = 0; s < HH * HH; s += 256) sW2[s + tid] = W2[s + tid];
    if (tid < HH) { sw1[tid] = w1[tid]; sb1[tid] = b1[tid]; sb2[tid] = b2[tid]; sw3[tid] = w3[tid]; }

    // zero accumulators (kernel boundary orders vs pair kernel)
    for (int idx = blockIdx.x * 256 + tid; idx < 12 * NN * 2; idx += BGRID * 256)
        g_vec[idx] = 0.f;
    if (blockIdx.x == 0 && tid < 64) g_slots[tid] = 0.0;
    __syncthreads();

    int quarter = tid & 3;
    int node    = tid >> 2;                  // 0..63
    int ridx = blockIdx.x * BSTRIDE + node;
    float r = (float)ridx * HSTEP;

    float h1[HH];
    #pragma unroll
    for (int k = 0; k < HH; k++)
        h1[k] = tanh_fast(fmaf(r, sw1[k], sb1[k]));

    float phi = 0.f, dphi = 0.f, d2phi = 0.f;
    {
        int c = quarter * 16;
        u64 z2[8], zp[8], zpp[8];
        #pragma unroll
        for (int p = 0; p < 8; p++) {
            z2[p]  = pack2f(sb2[c + 2 * p], sb2[c + 2 * p + 1]);
            zp[p]  = 0ull;
            zpp[p] = 0ull;
        }
        #pragma unroll
        for (int k = 0; k < HH; k++) {
            float h   = h1[k];
            float w1k = sw1[k];
            float s   = fmaf(-h, h, 1.f);
            float hp  = s * w1k;
            float hpp = -2.f * h * hp * w1k;
            u64 hh   = pack2(h);
            u64 hpx  = pack2(hp);
            u64 hppx = pack2(hpp);
            const ulonglong2* wr = (const ulonglong2*)(sW2 + k * HH + c);
            #pragma unroll
            for (int q = 0; q < 2; q++) {
                ulonglong2 wA = wr[2 * q];
                ulonglong2 wB = wr[2 * q + 1];
                z2[4 * q]      = fma2(wA.x, hh,   z2[4 * q]);
                z2[4 * q + 1]  = fma2(wA.y, hh,   z2[4 * q + 1]);
                z2[4 * q + 2]  = fma2(wB.x, hh,   z2[4 * q + 2]);
                z2[4 * q + 3]  = fma2(wB.y, hh,   z2[4 * q + 3]);
                zp[4 * q]      = fma2(wA.x, hpx,  zp[4 * q]);
                zp[4 * q + 1]  = fma2(wA.y, hpx,  zp[4 * q + 1]);
                zp[4 * q + 2]  = fma2(wB.x, hpx,  zp[4 * q + 2]);
                zp[4 * q + 3]  = fma2(wB.y, hpx,  zp[4 * q + 3]);
                zpp[4 * q]     = fma2(wA.x, hppx, zpp[4 * q]);
                zpp[4 * q + 1] = fma2(wA.y, hppx, zpp[4 * q + 1]);
                zpp[4 * q + 2] = fma2(wB.x, hppx, zpp[4 * q + 2]);
                zpp[4 * q + 3] = fma2(wB.y, hppx, zpp[4 * q + 3]);
            }
        }
        #pragma unroll
        for (int p = 0; p < 8; p++) {
            float a0, a1, p0, p1, q0, q1;
            unpack2(z2[p], a0, a1);
            unpack2(zp[p], p0, p1);
            unpack2(zpp[p], q0, q1);
            float w30 = sw3[c + 2 * p], w31 = sw3[c + 2 * p + 1];

            float h2 = tanh_fast(a0);
            phi = fmaf(w30, h2, phi);
            float e   = fmaf(-h2, h2, 1.f);
            float hp2 = e * p0;
            float hq2 = fmaf(e, q0, -2.f * h2 * hp2 * p0);
            dphi  = fmaf(w30, hp2, dphi);
            d2phi = fmaf(w30, hq2, d2phi);

            h2 = tanh_fast(a1);
            phi = fmaf(w31, h2, phi);
            e   = fmaf(-h2, h2, 1.f);
            hp2 = e * p1;
            hq2 = fmaf(e, q1, -2.f * h2 * hp2 * p1);
            dphi  = fmaf(w31, hp2, dphi);
            d2phi = fmaf(w31, hq2, d2phi);
        }
    }

    #pragma unroll
    for (int s = 1; s <= 2; s <<= 1) {
        phi   += __shfl_xor_sync(0xffffffffu, phi,   s);
        dphi  += __shfl_xor_sync(0xffffffffu, dphi,  s);
        d2phi += __shfl_xor_sync(0xffffffffu, d2phi, s);
    }

    if (quarter == 0) {
        sphi[node]  = phi + b3p[0];
        sdphi[node] = dphi;
        sd2[node]   = d2phi;
    }
    __syncthreads();

    if (quarter == 0 && node < BSTRIDE) {
        int e = blockIdx.x * BSTRIDE + node;
        if (e < NT)
            g_tab[e] = make_float4(sphi[node], sdphi[node], sd2[node],
                                   sd2[node + 1] - sd2[node]);
    }
}

// ------- triangle pair pass: 32x32 tiles, rotation-shuffle gradient exchange -------
#define PAIR_BODY(S, ACT)                                                     \
{                                                                             \
    int sj = (lane + (S)) & 31;                                               \
    float xjx = __shfl_sync(0xffffffffu, xjv.x, sj);                          \
    float xjy = __shfl_sync(0xffffffffu, xjv.y, sj);                          \
    float dx = xi.x - xjx, dy = xi.y - xjy;                                   \
    float ssq = fmaf(dx, dx, dy * dy);                                        \
    float inv = rsqrtf(fmaxf(ssq, 1e-20f));                                   \
    float rr = ssq * inv;                                                     \
    float uu = rr * scale;                                                    \
    int i0 = (int)uu; i0 = (i0 > NT - 2) ? (NT - 2) : i0;                     \
    float f = uu - (float)i0;                                                 \
    float4 e = __ldg(&g_tab[i0]);                                             \
    float x = f * HSTEP;                                                      \
    float d2 = fmaf(f, e.w, e.z);                                             \
    if (needphi) {                                                            \
        float ph = fmaf(x, fmaf(0.5f * x, fmaf(0.33333333f * f, e.w, e.z), e.y), e.x); \
        phis += (ACT) ? ph : 0.f;                                             \
    }                                                                         \
    if (deriv) {                                                              \
        lap += (ACT) ? d2 : 0.f;                                              \
        float dp = fmaf(x, fmaf(0.5f * f, e.w, e.z), e.y);                    \
        float c = dp * inv;                                                   \
        float cx = (ACT) ? c * dx : 0.f;                                      \
        float cy = (ACT) ? c * dy : 0.f;                                      \
        gax += cx; gay += cy;                                                 \
        int src = (lane - (S)) & 31;                                          \
        gbx -= __shfl_sync(0xffffffffu, cx, src);                             \
        gby -= __shfl_sync(0xffffffffu, cy, src);                             \
    }                                                                         \
}

__global__ void __launch_bounds__(256)
pair_tri(const float* __restrict__ data, const float* __restrict__ t_)
{
    int tid  = threadIdx.x;
    int w    = tid >> 5;
    int lane = tid & 31;
    int gw   = blockIdx.x * 8 + w;     // 0..1631
    int sl   = gw / JOBS;              // 0..11
    int job  = gw - sl * JOBS;
    int l    = sl % LL;
    bool deriv   = (l < LL - 1);
    bool needphi = (l == 0 || l == LL - 1);

    // decode (a<=b) tile pair from job; base(a) = a*(33-a)/2
    int a = (int)((33.f - sqrtf(1089.f - 8.f * (float)job)) * 0.5f);
    while ((a + 1) * (33 - (a + 1)) / 2 <= job) a++;
    while (a * (33 - a) / 2 > job) a--;
    int b = a + (job - a * (33 - a) / 2);
    bool diag = (a == b);

    const float2* snap = (const float2*)(data + (size_t)sl * NN * 2);
    float2 xi  = snap[a * 32 + lane];
    float2 xjv = diag ? xi : snap[b * 32 + lane];

    float gax = 0.f, gay = 0.f, gbx = 0.f, gby = 0.f;
    float lap = 0.f, phis = 0.f;
    const float scale = (float)NT / RMAX;

    if (diag) {
        #pragma unroll 4
        for (int s = 1; s <= 16; s++) {
            bool act = (s < 16) || (lane < 16);
            PAIR_BODY(s, act);
        }
    } else {
        #pragma unroll 4
        for (int s = 0; s < 32; s++) {
            PAIR_BODY(s, true);
        }
    }

    if (deriv) {
        float* gva = g_vec + sl * NN * 2;
        if (diag) {
            atomicAdd(&gva[(a * 32 + lane) * 2 + 0], gax + gbx);
            atomicAdd(&gva[(a * 32 + lane) * 2 + 1], gay + gby);
        } else {
            atomicAdd(&gva[(a * 32 + lane) * 2 + 0], gax);
            atomicAdd(&gva[(a * 32 + lane) * 2 + 1], gay);
            atomicAdd(&gva[(b * 32 + lane) * 2 + 0], gbx);
            atomicAdd(&gva[(b * 32 + lane) * 2 + 1], gby);
        }
    }

    #pragma unroll
    for (int k = 16; k > 0; k >>= 1) {
        lap  += __shfl_xor_sync(0xffffffffu, lap,  k);
        phis += __shfl_xor_sync(0xffffffffu, phis, k);
    }

    if (lane == 0 && (deriv || needphi)) {
        const double invN2 = 1.0 / ((double)NN * NN);
        double contrib = 0.0;
        if (deriv) {
            double dtl = (double)(t_[l + 1] - t_[l]);
            contrib += SIG2 * dtl * 2.0 * (double)lap * invN2;   // unordered -> x2
        }
        if (needphi) {
            double sign = (l == 0) ? 2.0 : -2.0;
            contrib += sign * 2.0 * (double)phis * invN2;
        }
        asm volatile("red.release.gpu.global.add.f64 [%0], %1;"
                     :: "l"(&g_slots[gw & 63]), "d"(contrib) : "memory");
    }
}

// ------- finalize: drift^2 from g_vec, V terms, slots, output -------
__global__ void __launch_bounds__(256)
finalize(const float* __restrict__ data, const float* __restrict__ t_,
         float* __restrict__ out)
{
    __shared__ double red[256];
    int tid = threadIdx.x;
    double ssum = 0.0;
    const double invN = 1.0 / (double)NN;

    if (tid < 64) ssum += g_slots[tid];

    for (int idx = tid; idx < MM * (LL - 1) * NN; idx += 256) {
        int i   = idx & (NN - 1);
        int dsl = idx >> 9;
        int l   = dsl % (LL - 1);
        int m   = dsl / (LL - 1);
        int sl  = m * LL + l;
        const float* snap = data + (size_t)sl * NN * 2;
        const float* gvp  = g_vec + sl * NN * 2 + i * 2;
        double dtl = (double)(t_[l + 1] - t_[l]);
        double drx = -(double)VK * (double)snap[i * 2 + 0] - (double)gvp[0] * invN;
        double dry = -(double)VK * (double)snap[i * 2 + 1] - (double)gvp[1] * invN;
        ssum += dtl * (drx * drx + dry * dry) * invN;
    }

    for (int idx = tid; idx < MM * 2 * NN; idx += 256) {
        int i  = idx & (NN - 1);
        int le = (idx >> 9) & 1;
        int m  = idx >> 10;
        int l  = le ? (LL - 1) : 0;
        double sign = le ? -2.0 : 2.0;
        const float* snap = data + (size_t)(m * LL + l) * NN * 2;
        double x = snap[i * 2 + 0], y = snap[i * 2 + 1];
        ssum += sign * 0.5 * (double)VK * (x * x + y * y) * invN;
    }

    red[tid] = ssum;
    __syncthreads();
    for (int k = 128; k > 0; k >>= 1) {
        if (tid < k) red[tid] += red[tid + k];
        __syncthreads();
    }
    if (tid == 0) {
        double S = red[0];
        S += (double)MM * SIG2 * (double)VK * DDIM * (double)(t_[LL - 1] - t_[0]);
        double res = S / (double)(MM * (LL - 1));
        out[0] = (float)(res * res);
    }
}

extern "C" void kernel_launch(void* const* d_in, const int* in_sizes, int n_in,
                              void* d_out, int out_size)
{
    const float* data = (const float*)d_in[0];
    const float* t    = (const float*)d_in[1];
    const float* w1   = (const float*)d_in[2];
    const float* b1   = (const float*)d_in[3];
    const float* W2   = (const float*)d_in[4];
    const float* b2   = (const float*)d_in[5];
    const float* w3   = (const float*)d_in[6];
    const float* b3   = (const float*)d_in[7];

    build_table<<<BGRID, 256>>>(w1, b1, W2, b2, w3, b3);
    pair_tri<<<NWJOB / 8, 256>>>(data, t);
    finalize<<<1, 256>>>(data, t, (float*)d_out);
}

// round 16
// speedup vs baseline: 1.8229x; 1.4239x over previous
#include <cuda_runtime.h>
#include <cstdint>

#define MM 2
#define LL 6
#define NN 512
#define HH 64
#define VK 1.0f
#define SIG2 0.01
#define DDIM 2.0
#define NT 2048
#define RMAX 16.0f
#define HSTEP (RMAX / (float)NT)
#define NWARP (MM * LL * NN)
#define BNODES 64
#define BSTRIDE 63
#define BGRID ((NT + BSTRIDE - 1) / BSTRIDE)   // 33

typedef unsigned long long u64;

__device__ float4 g_tab[NT];
__device__ double g_slots[64];
__device__ unsigned g_cnt;

__device__ __forceinline__ float tanh_fast(float x) {
    float y; asm("tanh.approx.f32 %0, %1;" : "=f"(y) : "f"(x)); return y;
}
__device__ __forceinline__ float rsqrt_fast(float x) {
    float y; asm("rsqrt.approx.f32 %0, %1;" : "=f"(y) : "f"(x)); return y;
}
__device__ __forceinline__ u64 pack2(float x) {
    u64 r; asm("mov.b64 %0, {%1,%1};" : "=l"(r) : "f"(x)); return r;
}
__device__ __forceinline__ u64 pack2f(float lo, float hi) {
    u64 r; asm("mov.b64 %0, {%1,%2};" : "=l"(r) : "f"(lo), "f"(hi)); return r;
}
__device__ __forceinline__ void unpack2(u64 v, float& lo, float& hi) {
    asm("mov.b64 {%0,%1}, %2;" : "=f"(lo), "=f"(hi) : "l"(v));
}
__device__ __forceinline__ u64 fma2(u64 a, u64 b, u64 c) {
    u64 d; asm("fma.rn.f32x2 %0, %1, %2, %3;" : "=l"(d) : "l"(a), "l"(b), "l"(c)); return d;
}

// ------- builder: 2-way split, h1 in registers, fused Taylor pack -------
__global__ void __launch_bounds__(128)
build_table(const float* __restrict__ w1, const float* __restrict__ b1,
            const float* __restrict__ W2, const float* __restrict__ b2,
            const float* __restrict__ w3, const float* __restrict__ b3p)
{
    __shared__ float sW2[HH * HH];
    __shared__ float sw1[HH], sb1[HH], sb2[HH], sw3[HH];
    __shared__ float sphi[BNODES], sdphi[BNODES], sd2[BNODES];

    int tid = threadIdx.x;
    #pragma unroll
    for (int s = 0; s < HH * HH; s += 128) sW2[s + tid] = W2[s + tid];
    if (tid < HH) { sw1[tid] = w1[tid]; sb1[tid] = b1[tid]; sb2[tid] = b2[tid]; sw3[tid] = w3[tid]; }

    if (blockIdx.x == 0) {
        if (tid < 64) g_slots[tid] = 0.0;
        if (tid == 64) g_cnt = 0u;
    }
    __syncthreads();

    int half = tid & 1;
    int pair = tid >> 1;
    int ridx = blockIdx.x * BSTRIDE + pair;
    float r = (float)ridx * HSTEP;

    float h1[HH];
    #pragma unroll
    for (int k = 0; k < HH; k++)
        h1[k] = tanh_fast(fmaf(r, sw1[k], sb1[k]));

    float phi = 0.f, dphi = 0.f, d2phi = 0.f;

    #pragma unroll
    for (int cc = 0; cc < 2; cc++) {
        int c = half * 32 + cc * 16;
        u64 z2[8], zp[8], zpp[8];
        #pragma unroll
        for (int p = 0; p < 8; p++) {
            z2[p]  = pack2f(sb2[c + 2 * p], sb2[c + 2 * p + 1]);
            zp[p]  = 0ull;
            zpp[p] = 0ull;
        }
        #pragma unroll 8
        for (int k = 0; k < HH; k++) {
            float h   = h1[k];
            float w1k = sw1[k];
            float s   = fmaf(-h, h, 1.f);
            float hp  = s * w1k;
            float hpp = -2.f * h * hp * w1k;
            u64 hh   = pack2(h);
            u64 hpx  = pack2(hp);
            u64 hppx = pack2(hpp);
            const ulonglong2* wr = (const ulonglong2*)(sW2 + k * HH + c);
            #pragma unroll
            for (int q = 0; q < 4; q++) {
                ulonglong2 w = wr[q];
                z2[2 * q]      = fma2(w.x, hh,   z2[2 * q]);
                z2[2 * q + 1]  = fma2(w.y, hh,   z2[2 * q + 1]);
                zp[2 * q]      = fma2(w.x, hpx,  zp[2 * q]);
                zp[2 * q + 1]  = fma2(w.y, hpx,  zp[2 * q + 1]);
                zpp[2 * q]     = fma2(w.x, hppx, zpp[2 * q]);
                zpp[2 * q + 1] = fma2(w.y, hppx, zpp[2 * q + 1]);
            }
        }
        #pragma unroll
        for (int p = 0; p < 8; p++) {
            float a0, a1, p0, p1, q0, q1;
            unpack2(z2[p], a0, a1);
            unpack2(zp[p], p0, p1);
            unpack2(zpp[p], q0, q1);
            float w30 = sw3[c + 2 * p], w31 = sw3[c + 2 * p + 1];

            float h2 = tanh_fast(a0);
            phi = fmaf(w30, h2, phi);
            float e   = fmaf(-h2, h2, 1.f);
            float hp2 = e * p0;
            float hq2 = fmaf(e, q0, -2.f * h2 * hp2 * p0);
            dphi  = fmaf(w30, hp2, dphi);
            d2phi = fmaf(w30, hq2, d2phi);

            h2 = tanh_fast(a1);
            phi = fmaf(w31, h2, phi);
            e   = fmaf(-h2, h2, 1.f);
            hp2 = e * p1;
            hq2 = fmaf(e, q1, -2.f * h2 * hp2 * p1);
            dphi  = fmaf(w31, hp2, dphi);
            d2phi = fmaf(w31, hq2, d2phi);
        }
    }

    phi   += __shfl_xor_sync(0xffffffffu, phi,   1);
    dphi  += __shfl_xor_sync(0xffffffffu, dphi,  1);
    d2phi += __shfl_xor_sync(0xffffffffu, d2phi, 1);

    if (half == 0) {
        sphi[pair]  = phi + b3p[0];
        sdphi[pair] = dphi;
        sd2[pair]   = d2phi;
    }
    __syncthreads();

    if (half == 0 && pair < BSTRIDE) {
        int e = blockIdx.x * BSTRIDE + pair;
        if (e < NT)
            g_tab[e] = make_float4(sphi[pair], sdphi[pair], sd2[pair],
                                   sd2[pair + 1] - sd2[pair]);
    }
}

// ------- pair pass: ordered pairs, warp-per-i, 4-batched gathers -------
__global__ void __launch_bounds__(256, 4)
pair_pass(const float* __restrict__ data, const float* __restrict__ t,
          float* __restrict__ out)
{
    __shared__ float2 sx[NN];

    int tid  = threadIdx.x;
    int w    = tid >> 5;
    int lane = tid & 31;
    int sl   = blockIdx.x >> 6;          // 0..11
    int i    = (blockIdx.x & 63) * 8 + w;
    int l    = sl % LL;
    int m    = sl / LL;
    bool deriv   = (l < LL - 1);
    bool needphi = (l == 0 || l == LL - 1);

    const float2* snap = (const float2*)(data + ((size_t)(m * LL + l)) * NN * 2);
    sx[tid]       = snap[tid];
    sx[tid + 256] = snap[tid + 256];
    __syncthreads();

    float2 xi = sx[i];
    float gx = 0.f, gy = 0.f, lap = 0.f, phis = 0.f;
    const float scale = (float)NT / RMAX;

    #pragma unroll
    for (int g = 0; g < 4; g++) {
        float4 es[4];
        float  fs[4], invs[4], dxs[4], dys[4];
        #pragma unroll
        for (int q = 0; q < 4; q++) {
            int j = lane + (g * 4 + q) * 32;
            float2 xj = sx[j];
            float dx = xi.x - xj.x, dy = xi.y - xj.y;
            float ssq = fmaf(dx, dx, dy * dy);
            float inv = rsqrt_fast(fmaxf(ssq, 1e-20f));
            float u = ssq * inv * scale;
            int i0 = (int)u;
            i0 = (i0 > NT - 2) ? (NT - 2) : i0;
            fs[q]   = u - (float)i0;
            invs[q] = inv;
            dxs[q]  = dx;
            dys[q]  = dy;
            es[q]   = __ldg(&g_tab[i0]);
        }
        #pragma unroll
        for (int q = 0; q < 4; q++) {
            int j = lane + (g * 4 + q) * 32;
            if (j != i) {
                float4 e = es[q];
                float f  = fs[q];
                float x  = f * HSTEP;
                float d2 = fmaf(f, e.w, e.z);
                float dp = fmaf(x, fmaf(0.5f * f, e.w, e.z), e.y);
                float ph = fmaf(x, fmaf(0.5f * x, fmaf(0.33333333f * f, e.w, e.z), e.y), e.x);
                phis += ph;
                lap  += d2;
                float c = dp * invs[q];
                gx = fmaf(c, dxs[q], gx);
                gy = fmaf(c, dys[q], gy);
            }
        }
    }

    #pragma unroll
    for (int s = 16; s > 0; s >>= 1) {
        gx   += __shfl_xor_sync(0xffffffffu, gx,   s);
        gy   += __shfl_xor_sync(0xffffffffu, gy,   s);
        lap  += __shfl_xor_sync(0xffffffffu, lap,  s);
        phis += __shfl_xor_sync(0xffffffffu, phis, s);
    }

    unsigned old = 0u;
    if (lane == 0) {
        double contrib = 0.0;
        if (deriv) {
            float dtl = t[l + 1] - t[l];
            float dgx = fmaf(-VK, xi.x, -gx / NN);
            float dgy = fmaf(-VK, xi.y, -gy / NN);
            contrib += (double)dtl * ((double)dgx * dgx + (double)dgy * dgy) / NN;
            contrib += SIG2 * (double)dtl * ((double)lap / NN) / NN;
        }
        if (needphi) {
            double sign = (l == 0) ? 2.0 : -2.0;
            contrib += sign * ((double)phis / ((double)NN * NN)
                             + 0.5 * (double)VK * ((double)xi.x * xi.x + (double)xi.y * xi.y) / NN);
        }
        asm volatile("red.release.gpu.global.add.f64 [%0], %1;"
                     :: "l"(&g_slots[i & 63]), "d"(contrib) : "memory");
        asm volatile("atom.acq_rel.gpu.global.add.u32 %0, [%1], %2;"
                     : "=r"(old) : "l"(&g_cnt), "r"(1u) : "memory");
    }
    old = __shfl_sync(0xffffffffu, old, 0);

    if (old == (unsigned)(NWARP - 1)) {
        double s0, s1;
        asm volatile("ld.acquire.gpu.global.f64 %0, [%1];"
                     : "=d"(s0) : "l"(&g_slots[lane]) : "memory");
        asm volatile("ld.acquire.gpu.global.f64 %0, [%1];"
                     : "=d"(s1) : "l"(&g_slots[lane + 32]) : "memory");
        double s = s0 + s1;
        #pragma unroll
        for (int k = 16; k > 0; k >>= 1) {
            double other;
            {
                u64 v = __double_as_longlong(s);
                uint32_t lo = (uint32_t)v, hi = (uint32_t)(v >> 32);
                lo = __shfl_xor_sync(0xffffffffu, lo, k);
                hi = __shfl_xor_sync(0xffffffffu, hi, k);
                other = __longlong_as_double(((u64)hi << 32) | lo);
            }
            s += other;
        }
        if (lane == 0) {
            s += (double)MM * SIG2 * (double)VK * DDIM * (double)(t[LL - 1] - t[0]);
            double res = s / (double)(MM * (LL - 1));
            out[0] = (float)(res * res);
        }
    }
}

extern "C" void kernel_launch(void* const* d_in, const int* in_sizes, int n_in,
                              void* d_out, int out_size)
{
    const float* data = (const float*)d_in[0];
    const float* t    = (const float*)d_in[1];
    const float* w1   = (const float*)d_in[2];
    const float* b1   = (const float*)d_in[3];
    const float* W2   = (const float*)d_in[4];
    const float* b2   = (const float*)d_in[5];
    const float* w3   = (const float*)d_in[6];
    const float* b3   = (const float*)d_in[7];

    build_table<<<BGRID, 128>>>(w1, b1, W2, b2, w3, b3);
    pair_pass<<<12 * 64, 256>>>(data, t, (float*)d_out);
}

// round 17
// speedup vs baseline: 2.1598x; 1.1848x over previous
#include <cuda_runtime.h>
#include <cstdint>

#define MM 2
#define LL 6
#define NN 512
#define HH 64
#define VK 1.0f
#define SIG2 0.01
#define DDIM 2.0
#define NT 2048
#define RMAX 16.0f
#define HSTEP (RMAX / (float)NT)
#define NWARP 6144            // pair warps (768 blocks x 8)
#define TBLK 137              // table-builder blocks
#define TSTRIDE 15            // table entries emitted per builder block
#define TNODES 16             // nodes computed per builder block (overlap 1)
#define PBLK 768              // pair blocks
#define GRID (TBLK + PBLK)

typedef unsigned long long u64;

__device__ float4 g_tab[NT];       // (phi+b3, dphi, d2, d2-slope)
__device__ double g_slots[64];
__device__ unsigned g_cnt;         // pair-warp completion counter
__device__ unsigned g_done;        // table-block completion counter

__device__ __forceinline__ float tanh_fast(float x) {
    float y; asm("tanh.approx.f32 %0, %1;" : "=f"(y) : "f"(x)); return y;
}
__device__ __forceinline__ float rsqrt_fast(float x) {
    float y; asm("rsqrt.approx.f32 %0, %1;" : "=f"(y) : "f"(x)); return y;
}
__device__ __forceinline__ u64 pack2(float x) {
    u64 r; asm("mov.b64 %0, {%1,%1};" : "=l"(r) : "f"(x)); return r;
}
__device__ __forceinline__ u64 pack2f(float lo, float hi) {
    u64 r; asm("mov.b64 %0, {%1,%2};" : "=l"(r) : "f"(lo), "f"(hi)); return r;
}
__device__ __forceinline__ void unpack2(u64 v, float& lo, float& hi) {
    asm("mov.b64 {%0,%1}, %2;" : "=f"(lo), "=f"(hi) : "l"(v));
}
__device__ __forceinline__ u64 fma2(u64 a, u64 b, u64 c) {
    u64 d; asm("fma.rn.f32x2 %0, %1, %2, %3;" : "=l"(d) : "l"(a), "l"(b), "l"(c)); return d;
}

#define ZROW 68                    // padded row (floats) for bank spread + v4 align

union SmemU {
    struct {
        float W2s[HH * HH];                    // 16 KB
        float w1s[HH], b1s[HH], b2s[HH], w3s[HH];
        float zbuf[3 * TNODES * ZROW];         // [stream][node][ch padded]
        float qbuf[TNODES * 4 * 3];            // per-(node,quarter) partials
        float nphi[TNODES], ndphi[TNODES], nd2[TNODES];
    } b;
    struct { float2 sx[NN]; } p;
};

__global__ void __launch_bounds__(256)
fused(const float* __restrict__ data, const float* __restrict__ t,
      const float* __restrict__ w1, const float* __restrict__ b1,
      const float* __restrict__ W2, const float* __restrict__ b2,
      const float* __restrict__ w3, const float* __restrict__ b3p,
      float* __restrict__ out)
{
    __shared__ SmemU sm;
    int tid = threadIdx.x;
    int bid = blockIdx.x;

    if (bid < TBLK) {
        // ---------------- table-builder block ----------------
        #pragma unroll
        for (int s = 0; s < HH * HH; s += 256) sm.b.W2s[s + tid] = W2[s + tid];
        if (tid < HH) {
            sm.b.w1s[tid] = w1[tid]; sm.b.b1s[tid] = b1[tid];
            sm.b.b2s[tid] = b2[tid]; sm.b.w3s[tid] = w3[tid];
        }
        __syncthreads();

        int node = tid & 15;
        int job  = tid >> 4;          // 0..15; 12..15 idle
        int stream = job >> 2;        // 0=z2, 1=zp, 2=zpp (for job<12)
        int q      = job & 3;

        if (job < 12) {
            int ridx = bid * TSTRIDE + node;
            float r = (float)ridx * HSTEP;

            u64 acc[8];
            #pragma unroll
            for (int p = 0; p < 8; p++)
                acc[p] = (stream == 0)
                       ? pack2f(sm.b.b2s[q * 16 + 2 * p], sm.b.b2s[q * 16 + 2 * p + 1])
                       : 0ull;

            #pragma unroll 8
            for (int k = 0; k < HH; k++) {
                float h = tanh_fast(fmaf(r, sm.b.w1s[k], sm.b.b1s[k]));
                float a;
                if (stream == 0) a = h;
                else {
                    float w1k = sm.b.w1s[k];
                    float e   = fmaf(-h, h, 1.f);
                    float hp  = e * w1k;
                    a = (stream == 1) ? hp : (-2.f * h * hp * w1k);
                }
                u64 av = pack2(a);
                const ulonglong2* wr = (const ulonglong2*)(sm.b.W2s + k * HH + q * 16);
                ulonglong2 wA = wr[0], wB = wr[1];
                acc[0] = fma2(wA.x, av, acc[0]);
                acc[1] = fma2(wA.y, av, acc[1]);
                acc[2] = fma2(wB.x, av, acc[2]);
                acc[3] = fma2(wB.y, av, acc[3]);
                wA = wr[2]; wB = wr[3];
                acc[4] = fma2(wA.x, av, acc[4]);
                acc[5] = fma2(wA.y, av, acc[5]);
                acc[6] = fma2(wB.x, av, acc[6]);
                acc[7] = fma2(wB.y, av, acc[7]);
            }
            float* dst = sm.b.zbuf + (stream * TNODES + node) * ZROW + q * 16;
            #pragma unroll
            for (int p = 0; p < 8; p++) {
                float lo, hi; unpack2(acc[p], lo, hi);
                dst[2 * p] = lo; dst[2 * p + 1] = hi;
            }
        }
        __syncthreads();

        // epilogue A: per (node, quarter) partial phi/dphi/d2
        if (tid < 64) {
            int node2 = tid & 15, q2 = tid >> 4;
            const float* z0 = sm.b.zbuf + (0 * TNODES + node2) * ZROW + q2 * 16;
            const float* z1 = sm.b.zbuf + (1 * TNODES + node2) * ZROW + q2 * 16;
            const float* z2 = sm.b.zbuf + (2 * TNODES + node2) * ZROW + q2 * 16;
            float phi = 0.f, dphi = 0.f, d2 = 0.f;
            #pragma unroll
            for (int ch = 0; ch < 16; ch++) {
                float z   = z0[ch];
                float zp  = z1[ch];
                float zpp = z2[ch];
                float h2  = tanh_fast(z);
                float e   = fmaf(-h2, h2, 1.f);
                float hp2 = e * zp;
                float hq2 = fmaf(e, zpp, -2.f * h2 * hp2 * zp);
                float w3v = sm.b.w3s[q2 * 16 + ch];
                phi  = fmaf(w3v, h2,  phi);
                dphi = fmaf(w3v, hp2, dphi);
                d2   = fmaf(w3v, hq2, d2);
            }
            float* qb = sm.b.qbuf + (node2 * 4 + q2) * 3;
            qb[0] = phi; qb[1] = dphi; qb[2] = d2;
        }
        __syncthreads();

        // epilogue B: combine quarters per node
        if (tid < TNODES) {
            float phi = 0.f, dphi = 0.f, d2 = 0.f;
            #pragma unroll
            for (int q2 = 0; q2 < 4; q2++) {
                const float* qb = sm.b.qbuf + (tid * 4 + q2) * 3;
                phi += qb[0]; dphi += qb[1]; d2 += qb[2];
            }
            sm.b.nphi[tid] = phi + b3p[0];
            sm.b.ndphi[tid] = dphi;
            sm.b.nd2[tid] = d2;
        }
        __syncthreads();

        if (tid < TSTRIDE) {
            int e = bid * TSTRIDE + tid;
            if (e < NT)
                g_tab[e] = make_float4(sm.b.nphi[tid], sm.b.ndphi[tid],
                                       sm.b.nd2[tid], sm.b.nd2[tid + 1] - sm.b.nd2[tid]);
        }
        __syncthreads();
        if (tid == 0) {
            unsigned dummy;
            asm volatile("atom.release.gpu.global.add.u32 %0, [%1], %2;"
                         : "=r"(dummy) : "l"(&g_done), "r"(1u) : "memory");
        }
        return;
    }

    // ---------------- pair block ----------------
    int pid  = bid - TBLK;
    int w    = tid >> 5;
    int lane = tid & 31;
    int sl   = pid >> 6;                 // 0..11
    int i    = (pid & 63) * 8 + w;
    int l    = sl % LL;
    int m    = sl / LL;
    bool deriv   = (l < LL - 1);
    bool needphi = (l == 0 || l == LL - 1);

    const float2* snap = (const float2*)(data + ((size_t)(m * LL + l)) * NN * 2);
    sm.p.sx[tid]       = snap[tid];
    sm.p.sx[tid + 256] = snap[tid + 256];

    // gate: wait for full table (table writes ordered by release/acquire)
    if (tid == 0) {
        unsigned v;
        while (true) {
            asm volatile("ld.acquire.gpu.global.u32 %0, [%1];" : "=r"(v) : "l"(&g_done));
            if (v >= (unsigned)TBLK) break;
            __nanosleep(64);
        }
    }
    __syncthreads();

    float2 xi = sm.p.sx[i];
    float gx = 0.f, gy = 0.f, lap = 0.f, phis = 0.f;
    const float scale = (float)NT / RMAX;

    #pragma unroll 8
    for (int jj = 0; jj < 16; jj++) {
        int j = lane + jj * 32;
        float2 xj = sm.p.sx[j];
        float dx = xi.x - xj.x, dy = xi.y - xj.y;
        float ssq = fmaf(dx, dx, dy * dy);
        if (j != i) {
            float inv = rsqrt_fast(fmaxf(ssq, 1e-20f));
            float u = ssq * inv * scale;
            int i0 = (int)u;
            i0 = (i0 > NT - 2) ? (NT - 2) : i0;
            float f = u - (float)i0;
            float4 e = __ldg(&g_tab[i0]);
            float x  = f * HSTEP;
            float d2 = fmaf(f, e.w, e.z);
            float dp = fmaf(x, fmaf(0.5f * f, e.w, e.z), e.y);
            float ph = fmaf(x, fmaf(0.5f * x, fmaf(0.33333333f * f, e.w, e.z), e.y), e.x);
            phis += ph;
            lap  += d2;
            float c = dp * inv;
            gx = fmaf(c, dx, gx);
            gy = fmaf(c, dy, gy);
        }
    }

    #pragma unroll
    for (int s = 16; s > 0; s >>= 1) {
        gx   += __shfl_xor_sync(0xffffffffu, gx,   s);
        gy   += __shfl_xor_sync(0xffffffffu, gy,   s);
        lap  += __shfl_xor_sync(0xffffffffu, lap,  s);
        phis += __shfl_xor_sync(0xffffffffu, phis, s);
    }

    unsigned old = 0u;
    if (lane == 0) {
        double contrib = 0.0;
        if (deriv) {
            float dtl = t[l + 1] - t[l];
            float dgx = fmaf(-VK, xi.x, -gx / NN);
            float dgy = fmaf(-VK, xi.y, -gy / NN);
            contrib += (double)dtl * ((double)dgx * dgx + (double)dgy * dgy) / NN;
            contrib += SIG2 * (double)dtl * ((double)lap / NN) / NN;
        }
        if (needphi) {
            double sign = (l == 0) ? 2.0 : -2.0;
            contrib += sign * ((double)phis / ((double)NN * NN)
                             + 0.5 * (double)VK * ((double)xi.x * xi.x + (double)xi.y * xi.y) / NN);
        }
        asm volatile("red.release.gpu.global.add.f64 [%0], %1;"
                     :: "l"(&g_slots[i & 63]), "d"(contrib) : "memory");
        asm volatile("atom.acq_rel.gpu.global.add.u32 %0, [%1], %2;"
                     : "=r"(old) : "l"(&g_cnt), "r"(1u) : "memory");
    }
    old = __shfl_sync(0xffffffffu, old, 0);

    if (old == (unsigned)(NWARP - 1)) {
        // winner warp: final reduce, output, reset state for next graph replay
        double s0, s1;
        asm volatile("ld.acquire.gpu.global.f64 %0, [%1];"
                     : "=d"(s0) : "l"(&g_slots[lane]) : "memory");
        asm volatile("ld.acquire.gpu.global.f64 %0, [%1];"
                     : "=d"(s1) : "l"(&g_slots[lane + 32]) : "memory");
        double s = s0 + s1;
        #pragma unroll
        for (int k = 16; k > 0; k >>= 1) {
            double other;
            {
                u64 v = __double_as_longlong(s);
                uint32_t lo = (uint32_t)v, hi = (uint32_t)(v >> 32);
                lo = __shfl_xor_sync(0xffffffffu, lo, k);
                hi = __shfl_xor_sync(0xffffffffu, hi, k);
                other = __longlong_as_double(((u64)hi << 32) | lo);
            }
            s += other;
        }
        // reset accumulators (all pair warps have already passed their adds)
        g_slots[lane] = 0.0;
        g_slots[lane + 32] = 0.0;
        if (lane == 0) {
            s += (double)MM * SIG2 * (double)VK * DDIM * (double)(t[LL - 1] - t[0]);
            double res = s / (double)(MM * (LL - 1));
            out[0] = (float)(res * res);
            asm volatile("st.relaxed.gpu.global.u32 [%0], %1;" :: "l"(&g_cnt), "r"(0u) : "memory");
            asm volatile("st.relaxed.gpu.global.u32 [%0], %1;" :: "l"(&g_done), "r"(0u) : "memory");
        }
    }
}

extern "C" void kernel_launch(void* const* d_in, const int* in_sizes, int n_in,
                              void* d_out, int out_size)
{
    const float* data = (const float*)d_in[0];
    const float* t    = (const float*)d_in[1];
    const float* w1   = (const float*)d_in[2];
    const float* b1   = (const float*)d_in[3];
    const float* W2   = (const float*)d_in[4];
    const float* b2   = (const float*)d_in[5];
    const float* w3   = (const float*)d_in[6];
    const float* b3   = (const float*)d_in[7];

    fused<<<GRID, 256>>>(data, t, w1, b1, W2, b2, w3, b3, (float*)d_out);
}